// round 1
// baseline (speedup 1.0000x reference)
#include <cuda_runtime.h>
#include <cstdint>

#define N_TOTAL 131072
#define L_LEV   8
#define NPL     16384
#define DEG     16
#define DIM     128
#define HID     64

// Scratch: inv-MLP outputs for all possible source nodes (levels 0..6), and
// per-level aggregated neighborhood features.
__device__ __align__(16) float g_inv[7 * NPL * DIM];     // 58.7 MB
__device__ __align__(16) float g_neigh[NPL * DIM];       // 8 MB

// ---------------------------------------------------------------------------
// Fused 3-layer MLP kernel: in[rows,128] -> LeakyReLU(in@w1+b1) -> LeakyReLU(.@w2+b2)
// -> .@w3+b3 -> out[rows,128].   Weights staged in shared memory.
// 64 rows per CTA, 256 threads.
// ---------------------------------------------------------------------------
#define RT 64
#define MLP_THREADS 256
// smem float layout offsets
#define OFF_W1 0
#define OFF_W2 (OFF_W1 + 128*64)
#define OFF_W3 (OFF_W2 + 64*64)
#define OFF_B1 (OFF_W3 + 64*128)
#define OFF_B2 (OFF_B1 + 64)
#define OFF_B3 (OFF_B2 + 64)
#define OFF_A  (OFF_B3 + 128)
#define OFF_B  (OFF_A + 64*128)
#define SMEM_FLOATS (OFF_B + 64*64)
#define SMEM_BYTES  (SMEM_FLOATS * 4)

__device__ __forceinline__ float leaky(float v) {
    return v >= 0.f ? v : 0.01f * v;
}

__device__ __forceinline__ void fma16(float acc[4], float4 x,
                                      float4 w0, float4 w1, float4 w2, float4 w3) {
    acc[0] = fmaf(x.x, w0.x, acc[0]); acc[0] = fmaf(x.y, w1.x, acc[0]);
    acc[0] = fmaf(x.z, w2.x, acc[0]); acc[0] = fmaf(x.w, w3.x, acc[0]);
    acc[1] = fmaf(x.x, w0.y, acc[1]); acc[1] = fmaf(x.y, w1.y, acc[1]);
    acc[1] = fmaf(x.z, w2.y, acc[1]); acc[1] = fmaf(x.w, w3.y, acc[1]);
    acc[2] = fmaf(x.x, w0.z, acc[2]); acc[2] = fmaf(x.y, w1.z, acc[2]);
    acc[2] = fmaf(x.z, w2.z, acc[2]); acc[2] = fmaf(x.w, w3.z, acc[2]);
    acc[3] = fmaf(x.x, w0.w, acc[3]); acc[3] = fmaf(x.y, w1.w, acc[3]);
    acc[3] = fmaf(x.z, w2.w, acc[3]); acc[3] = fmaf(x.w, w3.w, acc[3]);
}

__global__ __launch_bounds__(MLP_THREADS, 1)
void mlp_kernel(const float* __restrict__ in, float* __restrict__ out,
                const float* __restrict__ w1, const float* __restrict__ b1,
                const float* __restrict__ w2, const float* __restrict__ b2,
                const float* __restrict__ w3, const float* __restrict__ b3)
{
    extern __shared__ float sm[];
    float* w1s  = sm + OFF_W1;   // [128][64]
    float* w2s  = sm + OFF_W2;   // [64][64]
    float* w3s  = sm + OFF_W3;   // [64][128]
    float* b1s  = sm + OFF_B1;
    float* b2s  = sm + OFF_B2;
    float* b3s  = sm + OFF_B3;
    float* bufA = sm + OFF_A;    // [64][128] : input tile, then t2 (j<64)
    float* bufB = sm + OFF_B;    // [64][64]  : t1

    const int t = threadIdx.x;

    // Stage weights + biases
    for (int i = t; i < 128*64; i += MLP_THREADS) w1s[i] = w1[i];
    for (int i = t; i < 64*64;  i += MLP_THREADS) w2s[i] = w2[i];
    for (int i = t; i < 64*128; i += MLP_THREADS) w3s[i] = w3[i];
    if (t < 64)  { b1s[t] = b1[t]; b2s[t] = b2[t]; }
    if (t < 128) { b3s[t] = b3[t]; }

    // Stage input tile (64 rows x 128)
    const float4* in4 = (const float4*)(in + (size_t)blockIdx.x * RT * DIM);
    float4* a4 = (float4*)bufA;
    #pragma unroll
    for (int i = 0; i < (RT * DIM / 4) / MLP_THREADS; i++)
        a4[t + i * MLP_THREADS] = in4[t + i * MLP_THREADS];
    __syncthreads();

    // ---- Layer 1: bufA[64][128] @ w1[128][64] -> bufB[64][64], leaky ----
    {
        const int jq = t & 15, rg = t >> 4;
        const int j0 = jq * 4;
        float acc[4][4];
        #pragma unroll
        for (int rr = 0; rr < 4; rr++)
            #pragma unroll
            for (int jj = 0; jj < 4; jj++) acc[rr][jj] = b1s[j0 + jj];

        for (int k = 0; k < 128; k += 4) {
            float4 wv0 = *(const float4*)&w1s[(k + 0) * 64 + j0];
            float4 wv1 = *(const float4*)&w1s[(k + 1) * 64 + j0];
            float4 wv2 = *(const float4*)&w1s[(k + 2) * 64 + j0];
            float4 wv3 = *(const float4*)&w1s[(k + 3) * 64 + j0];
            #pragma unroll
            for (int rr = 0; rr < 4; rr++) {
                float4 xv = *(const float4*)&bufA[(rg * 4 + rr) * 128 + k];
                fma16(acc[rr], xv, wv0, wv1, wv2, wv3);
            }
        }
        #pragma unroll
        for (int rr = 0; rr < 4; rr++) {
            float4 o;
            o.x = leaky(acc[rr][0]); o.y = leaky(acc[rr][1]);
            o.z = leaky(acc[rr][2]); o.w = leaky(acc[rr][3]);
            *(float4*)&bufB[(rg * 4 + rr) * 64 + j0] = o;
        }
    }
    __syncthreads();

    // ---- Layer 2: bufB[64][64] @ w2[64][64] -> bufA[r*128 + j] (j<64), leaky ----
    {
        const int jq = t & 15, rg = t >> 4;
        const int j0 = jq * 4;
        float acc[4][4];
        #pragma unroll
        for (int rr = 0; rr < 4; rr++)
            #pragma unroll
            for (int jj = 0; jj < 4; jj++) acc[rr][jj] = b2s[j0 + jj];

        for (int k = 0; k < 64; k += 4) {
            float4 wv0 = *(const float4*)&w2s[(k + 0) * 64 + j0];
            float4 wv1 = *(const float4*)&w2s[(k + 1) * 64 + j0];
            float4 wv2 = *(const float4*)&w2s[(k + 2) * 64 + j0];
            float4 wv3 = *(const float4*)&w2s[(k + 3) * 64 + j0];
            #pragma unroll
            for (int rr = 0; rr < 4; rr++) {
                float4 xv = *(const float4*)&bufB[(rg * 4 + rr) * 64 + k];
                fma16(acc[rr], xv, wv0, wv1, wv2, wv3);
            }
        }
        __syncthreads();   // ensure all Layer-2 reads of bufB done before... (bufA writes below don't alias bufB, but bufA was fully consumed in L1; this sync orders L2 writes vs L3 reads via the next sync)
        #pragma unroll
        for (int rr = 0; rr < 4; rr++) {
            float4 o;
            o.x = leaky(acc[rr][0]); o.y = leaky(acc[rr][1]);
            o.z = leaky(acc[rr][2]); o.w = leaky(acc[rr][3]);
            *(float4*)&bufA[(rg * 4 + rr) * 128 + j0] = o;
        }
    }
    __syncthreads();

    // ---- Layer 3: bufA(t2)[64][64] @ w3[64][128] -> out, linear ----
    {
        const int jh = t & 31, rg3 = t >> 5;     // 8 row-groups x 8 rows
        const int j0 = jh * 4;
        float acc[8][4];
        #pragma unroll
        for (int rr = 0; rr < 8; rr++)
            #pragma unroll
            for (int jj = 0; jj < 4; jj++) acc[rr][jj] = b3s[j0 + jj];

        for (int k = 0; k < 64; k += 4) {
            float4 wv0 = *(const float4*)&w3s[(k + 0) * 128 + j0];
            float4 wv1 = *(const float4*)&w3s[(k + 1) * 128 + j0];
            float4 wv2 = *(const float4*)&w3s[(k + 2) * 128 + j0];
            float4 wv3 = *(const float4*)&w3s[(k + 3) * 128 + j0];
            #pragma unroll
            for (int rr = 0; rr < 8; rr++) {
                float4 xv = *(const float4*)&bufA[(rg3 * 8 + rr) * 128 + k];
                fma16(acc[rr], xv, wv0, wv1, wv2, wv3);
            }
        }
        float* outb = out + (size_t)blockIdx.x * RT * DIM;
        #pragma unroll
        for (int rr = 0; rr < 8; rr++) {
            float4 o;
            o.x = acc[rr][0]; o.y = acc[rr][1]; o.z = acc[rr][2]; o.w = acc[rr][3];
            *(float4*)&outb[(rg3 * 8 + rr) * 128 + j0] = o;
        }
    }
}

// ---------------------------------------------------------------------------
// Aggregation: one warp per destination node.
// neigh[v] = (1/16) * sum_e ( mask ? inv_h[src] : h[src] )
// ---------------------------------------------------------------------------
__global__ __launch_bounds__(256)
void agg_kernel(const float* __restrict__ h, const float* __restrict__ invh,
                const int* __restrict__ src, const int* __restrict__ mask,
                float* __restrict__ neigh)
{
    const int warp = (blockIdx.x * blockDim.x + threadIdx.x) >> 5;
    const int lane = threadIdx.x & 31;
    if (warp >= NPL) return;

    int s = 0, m = 0;
    if (lane < DEG) {
        s = src[warp * DEG + lane];
        m = mask[warp * DEG + lane];
    }

    float4 acc = make_float4(0.f, 0.f, 0.f, 0.f);
    #pragma unroll
    for (int e = 0; e < DEG; e++) {
        int se = __shfl_sync(0xffffffffu, s, e);
        int me = __shfl_sync(0xffffffffu, m, e);
        const float4* row = (const float4*)((me ? invh : h) + (size_t)se * DIM);
        float4 v = row[lane];
        acc.x += v.x; acc.y += v.y; acc.z += v.z; acc.w += v.w;
    }
    const float s16 = 1.0f / 16.0f;
    acc.x *= s16; acc.y *= s16; acc.z *= s16; acc.w *= s16;
    ((float4*)(neigh + (size_t)warp * DIM))[lane] = acc;
}

// ---------------------------------------------------------------------------
extern "C" void kernel_launch(void* const* d_in, const int* in_sizes, int n_in,
                              void* d_out, int out_size)
{
    const float* h_in  = (const float*)d_in[0];
    const int*   esrc  = (const int*)d_in[1];
    const int*   emask = (const int*)d_in[2];
    const float* iw1 = (const float*)d_in[3];
    const float* ib1 = (const float*)d_in[4];
    const float* iw2 = (const float*)d_in[5];
    const float* ib2 = (const float*)d_in[6];
    const float* iw3 = (const float*)d_in[7];
    const float* ib3 = (const float*)d_in[8];
    const float* aw1 = (const float*)d_in[9];
    const float* ab1 = (const float*)d_in[10];
    const float* aw2 = (const float*)d_in[11];
    const float* ab2 = (const float*)d_in[12];
    const float* aw3 = (const float*)d_in[13];
    const float* ab3 = (const float*)d_in[14];

    float* h = (float*)d_out;

    float* ginv = nullptr;
    float* gneigh = nullptr;
    cudaGetSymbolAddress((void**)&ginv, g_inv);
    cudaGetSymbolAddress((void**)&gneigh, g_neigh);

    cudaFuncSetAttribute(mlp_kernel, cudaFuncAttributeMaxDynamicSharedMemorySize,
                         SMEM_BYTES);

    // h_out starts as a copy of input h (level-0 rows survive; rest overwritten)
    cudaMemcpyAsync(h, h_in, (size_t)N_TOTAL * DIM * sizeof(float),
                    cudaMemcpyDeviceToDevice, 0);

    const int mlp_grid = NPL / RT;               // 256
    const int agg_grid = (NPL * 32) / 256;       // 2048 blocks of 8 warps

    // inv features for level-0 nodes
    mlp_kernel<<<mlp_grid, MLP_THREADS, SMEM_BYTES>>>(
        h, ginv, iw1, ib1, iw2, ib2, iw3, ib3);

    for (int lvl = 0; lvl < L_LEV - 1; lvl++) {
        const int* s = esrc  + (size_t)lvl * NPL * DEG;
        const int* m = emask + (size_t)lvl * NPL * DEG;

        agg_kernel<<<agg_grid, 256>>>(h, ginv, s, m, gneigh);

        float* dst = h + (size_t)(lvl + 1) * NPL * DIM;
        mlp_kernel<<<mlp_grid, MLP_THREADS, SMEM_BYTES>>>(
            gneigh, dst, aw1, ab1, aw2, ab2, aw3, ab3);

        if (lvl < L_LEV - 2) {
            float* idst = ginv + (size_t)(lvl + 1) * NPL * DIM;
            mlp_kernel<<<mlp_grid, MLP_THREADS, SMEM_BYTES>>>(
                dst, idst, iw1, ib1, iw2, ib2, iw3, ib3);
        }
    }
}

// round 2
// speedup vs baseline: 1.7015x; 1.7015x over previous
#include <cuda_runtime.h>
#include <cstdint>

#define NPL   16384
#define DEG   16
#define DIM   128
#define HID   64
#define L_LEV 8
#define NT    256
#define RT    64

// inv-MLP outputs for all potential source nodes (levels 0..6), absolute node id
__device__ __align__(16) float g_inv[7 * NPL * DIM];   // 58.7 MB

// ---- shared memory layout (floats) ----
#define OW   0                 // weights, max 128*64 = 8192 floats (32 KB)
#define OB   (OW + 8192)       // bias, max 128
#define OA   (OB + 128)        // bufA 64x128
#define OBB  (OA + 8192)       // bufB 64x64
#define SM_FLOATS (OBB + 4096)
#define SM_BYTES  (SM_FLOATS * 4)   // 82432 B -> 2 CTAs/SM

__device__ __forceinline__ float leaky(float v) { return v >= 0.f ? v : 0.01f * v; }

__device__ __forceinline__ void ffma2(uint64_t& d, uint64_t a, uint64_t b) {
    asm("fma.rn.f32x2 %0, %1, %2, %0;" : "+l"(d) : "l"(a), "l"(b));
}
__device__ __forceinline__ uint64_t pack2(float x) {
    uint64_t r; asm("mov.b64 %0, {%1, %1};" : "=l"(r) : "f"(x)); return r;
}
__device__ __forceinline__ float2 unpack2(uint64_t p) {
    float2 v; asm("mov.b64 {%0, %1}, %2;" : "=f"(v.x), "=f"(v.y) : "l"(p)); return v;
}

// ---- weight staging (per layer) ----
__device__ __forceinline__ void stage_w(float* sw, const float* w, int nw,
                                        float* sb, const float* b, int nb, int t) {
    const float4* w4 = (const float4*)w;
    float4* s4 = (float4*)sw;
    for (int i = t; i < nw / 4; i += NT) s4[i] = w4[i];
    if (t < nb) sb[t] = b[t];
}

// ---- Layer: [64,128] @ [128,64] + b, LeakyReLU.  in stride 128, out stride 64.
__device__ __forceinline__ void layer_128_64(const float* __restrict__ in,
                                             const float* __restrict__ w,
                                             const float* __restrict__ b,
                                             float* __restrict__ out, int t) {
    const int j0 = (t & 15) * 4;
    const int r0 = (t >> 4) * 4;
    uint64_t acc[4][2];
    const uint64_t b0 = *(const uint64_t*)&b[j0];
    const uint64_t b1 = *(const uint64_t*)&b[j0 + 2];
#pragma unroll
    for (int rr = 0; rr < 4; rr++) { acc[rr][0] = b0; acc[rr][1] = b1; }
#pragma unroll 4
    for (int k = 0; k < 128; k += 4) {
        uint64_t wl[4], wh[4];
#pragma unroll
        for (int kk = 0; kk < 4; kk++) {
            const uint64_t* wp = (const uint64_t*)&w[(k + kk) * 64 + j0];
            wl[kk] = wp[0]; wh[kk] = wp[1];
        }
#pragma unroll
        for (int rr = 0; rr < 4; rr++) {
            float4 xv = *(const float4*)&in[(r0 + rr) * 128 + k];
            uint64_t xx;
            xx = pack2(xv.x); ffma2(acc[rr][0], xx, wl[0]); ffma2(acc[rr][1], xx, wh[0]);
            xx = pack2(xv.y); ffma2(acc[rr][0], xx, wl[1]); ffma2(acc[rr][1], xx, wh[1]);
            xx = pack2(xv.z); ffma2(acc[rr][0], xx, wl[2]); ffma2(acc[rr][1], xx, wh[2]);
            xx = pack2(xv.w); ffma2(acc[rr][0], xx, wl[3]); ffma2(acc[rr][1], xx, wh[3]);
        }
    }
#pragma unroll
    for (int rr = 0; rr < 4; rr++) {
        float2 p0 = unpack2(acc[rr][0]);
        float2 p1 = unpack2(acc[rr][1]);
        float4 o = make_float4(leaky(p0.x), leaky(p0.y), leaky(p1.x), leaky(p1.y));
        *(float4*)&out[(r0 + rr) * 64 + j0] = o;
    }
}

// ---- Layer: [64,64] @ [64,64] + b, LeakyReLU. IN-PLACE SAFE (sync before store).
__device__ __forceinline__ void layer_64_64(const float* __restrict__ in,
                                            const float* __restrict__ w,
                                            const float* __restrict__ b,
                                            float* __restrict__ out, int t) {
    const int j0 = (t & 15) * 4;
    const int r0 = (t >> 4) * 4;
    uint64_t acc[4][2];
    const uint64_t b0 = *(const uint64_t*)&b[j0];
    const uint64_t b1 = *(const uint64_t*)&b[j0 + 2];
#pragma unroll
    for (int rr = 0; rr < 4; rr++) { acc[rr][0] = b0; acc[rr][1] = b1; }
#pragma unroll 4
    for (int k = 0; k < 64; k += 4) {
        uint64_t wl[4], wh[4];
#pragma unroll
        for (int kk = 0; kk < 4; kk++) {
            const uint64_t* wp = (const uint64_t*)&w[(k + kk) * 64 + j0];
            wl[kk] = wp[0]; wh[kk] = wp[1];
        }
#pragma unroll
        for (int rr = 0; rr < 4; rr++) {
            float4 xv = *(const float4*)&in[(r0 + rr) * 64 + k];
            uint64_t xx;
            xx = pack2(xv.x); ffma2(acc[rr][0], xx, wl[0]); ffma2(acc[rr][1], xx, wh[0]);
            xx = pack2(xv.y); ffma2(acc[rr][0], xx, wl[1]); ffma2(acc[rr][1], xx, wh[1]);
            xx = pack2(xv.z); ffma2(acc[rr][0], xx, wl[2]); ffma2(acc[rr][1], xx, wh[2]);
            xx = pack2(xv.w); ffma2(acc[rr][0], xx, wl[3]); ffma2(acc[rr][1], xx, wh[3]);
        }
    }
    __syncthreads();   // all reads of `in` done before anyone overwrites it
#pragma unroll
    for (int rr = 0; rr < 4; rr++) {
        float2 p0 = unpack2(acc[rr][0]);
        float2 p1 = unpack2(acc[rr][1]);
        float4 o = make_float4(leaky(p0.x), leaky(p0.y), leaky(p1.x), leaky(p1.y));
        *(float4*)&out[(r0 + rr) * 64 + j0] = o;
    }
}

// ---- Layer: [64,64] @ [64,128] + b, linear. out -> gmem (+ optional smem stride 128)
template <bool SMEM_OUT>
__device__ __forceinline__ void layer_64_128(const float* __restrict__ in,
                                             const float* __restrict__ w,
                                             const float* __restrict__ b,
                                             float* __restrict__ outS,
                                             float* __restrict__ outG, int t) {
    const int j0 = (t & 31) * 4;
    const int r0 = (t >> 5) * 8;
    uint64_t acc[8][2];
    const uint64_t b0 = *(const uint64_t*)&b[j0];
    const uint64_t b1 = *(const uint64_t*)&b[j0 + 2];
#pragma unroll
    for (int rr = 0; rr < 8; rr++) { acc[rr][0] = b0; acc[rr][1] = b1; }
#pragma unroll 4
    for (int k = 0; k < 64; k += 4) {
        uint64_t wl[4], wh[4];
#pragma unroll
        for (int kk = 0; kk < 4; kk++) {
            const uint64_t* wp = (const uint64_t*)&w[(k + kk) * 128 + j0];
            wl[kk] = wp[0]; wh[kk] = wp[1];
        }
#pragma unroll
        for (int rr = 0; rr < 8; rr++) {
            float4 xv = *(const float4*)&in[(r0 + rr) * 64 + k];
            uint64_t xx;
            xx = pack2(xv.x); ffma2(acc[rr][0], xx, wl[0]); ffma2(acc[rr][1], xx, wh[0]);
            xx = pack2(xv.y); ffma2(acc[rr][0], xx, wl[1]); ffma2(acc[rr][1], xx, wh[1]);
            xx = pack2(xv.z); ffma2(acc[rr][0], xx, wl[2]); ffma2(acc[rr][1], xx, wh[2]);
            xx = pack2(xv.w); ffma2(acc[rr][0], xx, wl[3]); ffma2(acc[rr][1], xx, wh[3]);
        }
    }
#pragma unroll
    for (int rr = 0; rr < 8; rr++) {
        float2 p0 = unpack2(acc[rr][0]);
        float2 p1 = unpack2(acc[rr][1]);
        float4 o = make_float4(p0.x, p0.y, p1.x, p1.y);
        if (SMEM_OUT) *(float4*)&outS[(r0 + rr) * 128 + j0] = o;
        *(float4*)&outG[(r0 + rr) * 128 + j0] = o;
    }
}

// ---------------------------------------------------------------------------
// Fused per-level kernel: gather+mean -> and-MLP (-> h, smem) -> inv-MLP (-> g_inv)
// ---------------------------------------------------------------------------
__global__ __launch_bounds__(NT, 2)
void level_kernel(float* __restrict__ h, float* __restrict__ ginv,
                  const int* __restrict__ src, const int* __restrict__ mask,
                  int lvl, int do_inv,
                  const float* aw1, const float* ab1, const float* aw2, const float* ab2,
                  const float* aw3, const float* ab3,
                  const float* iw1, const float* ib1, const float* iw2, const float* ib2,
                  const float* iw3, const float* ib3)
{
    extern __shared__ float sm[];
    float* W  = sm + OW;
    float* B  = sm + OB;
    float* A  = sm + OA;
    float* Bf = sm + OBB;
    const int t = threadIdx.x;

    // stage and_w1 (no dependency on gather)
    stage_w(W, aw1, 128 * 64, B, ab1, 64, t);

    // ---- gather + masked-select + mean into A[64][128] ----
    {
        const int warp = t >> 5, lane = t & 31;
        const int nodebase = blockIdx.x * RT;
#pragma unroll
        for (int rr = 0; rr < 8; rr++) {
            const int r = warp * 8 + rr;
            const int node = nodebase + r;
            int s = 0, m = 0;
            if (lane < 16) {
                s = src[node * DEG + lane];
                m = mask[node * DEG + lane];
            }
            float4 acc = make_float4(0.f, 0.f, 0.f, 0.f);
#pragma unroll
            for (int e = 0; e < DEG; e++) {
                int se = __shfl_sync(0xffffffffu, s, e);
                int me = __shfl_sync(0xffffffffu, m, e);
                const float4* row = (const float4*)((me ? ginv : h) + (size_t)se * DIM);
                float4 v = row[lane];
                acc.x += v.x; acc.y += v.y; acc.z += v.z; acc.w += v.w;
            }
            const float s16 = 0.0625f;
            acc.x *= s16; acc.y *= s16; acc.z *= s16; acc.w *= s16;
            *(float4*)&A[r * 128 + lane * 4] = acc;
        }
    }
    __syncthreads();

    // ---- and-MLP ----
    layer_128_64(A, W, B, Bf, t);
    __syncthreads();
    stage_w(W, aw2, 64 * 64, B, ab2, 64, t);
    __syncthreads();
    layer_64_64(Bf, W, B, Bf, t);         // internal sync before store
    __syncthreads();
    stage_w(W, aw3, 64 * 128, B, ab3, 128, t);
    __syncthreads();
    float* hdst = h + ((size_t)(lvl + 1) * NPL + (size_t)blockIdx.x * RT) * DIM;
    layer_64_128<true>(Bf, W, B, A, hdst, t);
    __syncthreads();

    if (do_inv) {
        // ---- inv-MLP on the fresh h tile (in A) ----
        stage_w(W, iw1, 128 * 64, B, ib1, 64, t);
        __syncthreads();
        layer_128_64(A, W, B, Bf, t);
        __syncthreads();
        stage_w(W, iw2, 64 * 64, B, ib2, 64, t);
        __syncthreads();
        layer_64_64(Bf, W, B, Bf, t);
        __syncthreads();
        stage_w(W, iw3, 64 * 128, B, ib3, 128, t);
        __syncthreads();
        float* gdst = ginv + ((size_t)(lvl + 1) * NPL + (size_t)blockIdx.x * RT) * DIM;
        layer_64_128<false>(Bf, W, B, nullptr, gdst, t);
    }
}

// ---------------------------------------------------------------------------
// Initial kernel: inv-MLP over level-0 rows of the input h.
// ---------------------------------------------------------------------------
__global__ __launch_bounds__(NT, 2)
void inv0_kernel(const float* __restrict__ hin, float* __restrict__ ginv,
                 const float* iw1, const float* ib1, const float* iw2, const float* ib2,
                 const float* iw3, const float* ib3)
{
    extern __shared__ float sm[];
    float* W  = sm + OW;
    float* B  = sm + OB;
    float* A  = sm + OA;
    float* Bf = sm + OBB;
    const int t = threadIdx.x;

    stage_w(W, iw1, 128 * 64, B, ib1, 64, t);

    const float4* in4 = (const float4*)(hin + (size_t)blockIdx.x * RT * DIM);
    float4* a4 = (float4*)A;
#pragma unroll
    for (int i = 0; i < (RT * DIM / 4) / NT; i++)
        a4[t + i * NT] = in4[t + i * NT];
    __syncthreads();

    layer_128_64(A, W, B, Bf, t);
    __syncthreads();
    stage_w(W, iw2, 64 * 64, B, ib2, 64, t);
    __syncthreads();
    layer_64_64(Bf, W, B, Bf, t);
    __syncthreads();
    stage_w(W, iw3, 64 * 128, B, ib3, 128, t);
    __syncthreads();
    float* gdst = ginv + (size_t)blockIdx.x * RT * DIM;
    layer_64_128<false>(Bf, W, B, nullptr, gdst, t);
}

// ---------------------------------------------------------------------------
extern "C" void kernel_launch(void* const* d_in, const int* in_sizes, int n_in,
                              void* d_out, int out_size)
{
    const float* h_in  = (const float*)d_in[0];
    const int*   esrc  = (const int*)d_in[1];
    const int*   emask = (const int*)d_in[2];
    const float* iw1 = (const float*)d_in[3];
    const float* ib1 = (const float*)d_in[4];
    const float* iw2 = (const float*)d_in[5];
    const float* ib2 = (const float*)d_in[6];
    const float* iw3 = (const float*)d_in[7];
    const float* ib3 = (const float*)d_in[8];
    const float* aw1 = (const float*)d_in[9];
    const float* ab1 = (const float*)d_in[10];
    const float* aw2 = (const float*)d_in[11];
    const float* ab2 = (const float*)d_in[12];
    const float* aw3 = (const float*)d_in[13];
    const float* ab3 = (const float*)d_in[14];

    float* h = (float*)d_out;
    float* ginv = nullptr;
    cudaGetSymbolAddress((void**)&ginv, g_inv);

    static bool attr_set = false;
    if (!attr_set) {
        cudaFuncSetAttribute(level_kernel, cudaFuncAttributeMaxDynamicSharedMemorySize, SM_BYTES);
        cudaFuncSetAttribute(inv0_kernel,  cudaFuncAttributeMaxDynamicSharedMemorySize, SM_BYTES);
        attr_set = true;
    }

    // only level-0 rows survive from the input; levels 1..7 are fully overwritten
    cudaMemcpyAsync(h, h_in, (size_t)NPL * DIM * sizeof(float),
                    cudaMemcpyDeviceToDevice, 0);

    const int grid = NPL / RT;   // 256

    inv0_kernel<<<grid, NT, SM_BYTES>>>(h_in, ginv, iw1, ib1, iw2, ib2, iw3, ib3);

    for (int lvl = 0; lvl < L_LEV - 1; lvl++) {
        const int* s = esrc  + (size_t)lvl * NPL * DEG;
        const int* m = emask + (size_t)lvl * NPL * DEG;
        level_kernel<<<grid, NT, SM_BYTES>>>(
            h, ginv, s, m, lvl, (lvl < L_LEV - 2) ? 1 : 0,
            aw1, ab1, aw2, ab2, aw3, ab3,
            iw1, ib1, iw2, ib2, iw3, ib3);
    }
}

// round 4
// speedup vs baseline: 2.3381x; 1.3741x over previous
#include <cuda_runtime.h>
#include <cuda_bf16.h>
#include <cstdint>

#define NPL   16384
#define DEG   16
#define DIM   128
#define L_LEV 8
#define NT    256

// byte strides (row pitch) — 16B pad keeps ldmatrix rows 4 banks apart
#define STR_A 272    // 128 bf16 + 16B pad
#define STR_B 144    // 64  bf16 + 16B pad

// per-MLP weight blob offsets (bytes): [N][K] bf16, padded stride
#define WL1H 0
#define WL1L 17408          // 64 * 272
#define WL2H 34816
#define WL2L 44032          // +64*144
#define WL3H 53248
#define WL3L 71680          // +128*144
#define WBLOB 90112

// smem layout (bytes)
#define OFF_W    0                       // staged weights (hi|lo), max 36864
#define OFF_AH   36864                   // activation A hi [64][STR_A]
#define OFF_AL   (OFF_AH + 17408)
#define OFF_BH   (OFF_AL + 17408)        // activation B hi [64][STR_B]
#define OFF_BL   (OFF_BH + 9216)
#define OFF_BIAS (OFF_BL + 9216)         // 512 floats
#define SM_TOTAL (OFF_BIAS + 2048)       // 92160 B -> 2 CTAs/SM

__device__ __align__(16) float   g_inv[7 * NPL * DIM];   // inv-MLP outputs per node
__device__ __align__(16) uint8_t g_wb[2 * WBLOB];        // bf16 hi/lo weights (and, inv)

__device__ __forceinline__ float leaky(float v) { return v >= 0.f ? v : 0.01f * v; }

__device__ __forceinline__ void split2(float f0, float f1, uint32_t& hi, uint32_t& lo) {
    __nv_bfloat16 h0 = __float2bfloat16(f0);
    __nv_bfloat16 h1 = __float2bfloat16(f1);
    float r0 = f0 - __bfloat162float(h0);
    float r1 = f1 - __bfloat162float(h1);
    __nv_bfloat16 l0 = __float2bfloat16(r0);
    __nv_bfloat16 l1 = __float2bfloat16(r1);
    hi = (uint32_t)__bfloat16_as_ushort(h0) | ((uint32_t)__bfloat16_as_ushort(h1) << 16);
    lo = (uint32_t)__bfloat16_as_ushort(l0) | ((uint32_t)__bfloat16_as_ushort(l1) << 16);
}

__device__ __forceinline__ uint32_t smem_u32(const void* p) {
    uint32_t a;
    asm("{ .reg .u64 t; cvta.to.shared.u64 t, %1; cvt.u32.u64 %0, t; }" : "=r"(a) : "l"(p));
    return a;
}
__device__ __forceinline__ void ldm4(uint32_t addr, uint32_t r[4]) {
    asm volatile("ldmatrix.sync.aligned.m8n8.x4.shared.b16 {%0,%1,%2,%3}, [%4];"
                 : "=r"(r[0]), "=r"(r[1]), "=r"(r[2]), "=r"(r[3]) : "r"(addr));
}
__device__ __forceinline__ void mma16816(float c[4], const uint32_t a[4],
                                         uint32_t b0, uint32_t b1) {
    asm volatile("mma.sync.aligned.m16n8k16.row.col.f32.bf16.bf16.f32 "
                 "{%0,%1,%2,%3}, {%4,%5,%6,%7}, {%8,%9}, {%0,%1,%2,%3};"
                 : "+f"(c[0]), "+f"(c[1]), "+f"(c[2]), "+f"(c[3])
                 : "r"(a[0]), "r"(a[1]), "r"(a[2]), "r"(a[3]), "r"(b0), "r"(b1));
}

// ---------------- weight prep: fp32 [K][N] -> bf16 hi/lo [N][K] padded ----------------
__global__ void prep_weights(const float* aw1, const float* aw2, const float* aw3,
                             const float* iw1, const float* iw2, const float* iw3)
{
    const int b = blockIdx.x;          // 0..2 and, 3..5 inv
    const int layer = b % 3;
    const uint32_t base = (b < 3) ? 0u : (uint32_t)WBLOB;
    const float* W; int K, N; uint32_t stride, offH, offL;
    if (layer == 0)      { K = 128; N = 64;  stride = STR_A; offH = WL1H; offL = WL1L; W = (b < 3) ? aw1 : iw1; }
    else if (layer == 1) { K = 64;  N = 64;  stride = STR_B; offH = WL2H; offL = WL2L; W = (b < 3) ? aw2 : iw2; }
    else                 { K = 64;  N = 128; stride = STR_B; offH = WL3H; offL = WL3L; W = (b < 3) ? aw3 : iw3; }
    uint8_t* oH = g_wb + base + offH;
    uint8_t* oL = g_wb + base + offL;
    const int slots = N * (int)(stride / 2);
    for (int idx = threadIdx.x; idx < slots; idx += blockDim.x) {
        int n = idx / (stride / 2);
        int s = idx % (stride / 2);
        __nv_bfloat16 hv = __float2bfloat16(0.f), lv = __float2bfloat16(0.f);
        if (s < K) {
            float f = W[s * N + n];
            hv = __float2bfloat16(f);
            lv = __float2bfloat16(f - __bfloat162float(hv));
        }
        *(__nv_bfloat16*)(oH + (size_t)n * stride + (size_t)s * 2) = hv;
        *(__nv_bfloat16*)(oL + (size_t)n * stride + (size_t)s * 2) = lv;
    }
}

// ---------------- warp-tile GEMM: C[16 x NB8*8] += (Ah+Al)@(Bh+Bl)^T ----------------
template <int KSTEPS, int NB8>
__device__ __forceinline__ void mma_layer(uint32_t aHi, uint32_t aLo, uint32_t strideA,
                                          uint32_t wHi, uint32_t wLo, uint32_t strideB,
                                          int mt, int n0, int lane, float acc[][4])
{
#pragma unroll
    for (int i = 0; i < NB8; i++) { acc[i][0] = acc[i][1] = acc[i][2] = acc[i][3] = 0.f; }
    const uint32_t aRow = (uint32_t)(mt * 16 + (lane & 15)) * strideA + (uint32_t)(lane >> 4) * 16u;
#pragma unroll
    for (int kb = 0; kb < KSTEPS; kb++) {
        uint32_t ah[4], al[4];
        ldm4(aHi + aRow + (uint32_t)kb * 32u, ah);
        ldm4(aLo + aRow + (uint32_t)kb * 32u, al);
#pragma unroll
        for (int s = 0; s < NB8 / 4; s++) {
            const uint32_t bRow = (uint32_t)(n0 + s * 32 + lane) * strideB + (uint32_t)kb * 32u;
            uint32_t bh0[4], bh1[4], bl0[4], bl1[4];
            ldm4(wHi + bRow, bh0);
            ldm4(wHi + bRow + 16u, bh1);
            ldm4(wLo + bRow, bl0);
            ldm4(wLo + bRow + 16u, bl1);
#pragma unroll
            for (int nf = 0; nf < 4; nf++) {
                mma16816(acc[s * 4 + nf], ah, bh0[nf], bh1[nf]);
                mma16816(acc[s * 4 + nf], ah, bl0[nf], bl1[nf]);
                mma16816(acc[s * 4 + nf], al, bh0[nf], bh1[nf]);
            }
        }
    }
}

// ---------------- mid-layer epilogue: bias + leaky + split -> smem hi/lo ----------------
template <int NB8>
__device__ __forceinline__ void epi_mid(const float acc[][4], const float* bias,
                                        uint8_t* smem, uint32_t outHi, uint32_t outLo,
                                        uint32_t strideOut, int mt, int n0, int lane)
{
    const int qr = lane >> 2, qc = (lane & 3) * 2;
#pragma unroll
    for (int nf = 0; nf < NB8; nf++) {
        const int col = n0 + nf * 8 + qc;
        const float b0 = bias[col], b1 = bias[col + 1];
#pragma unroll
        for (int hf = 0; hf < 2; hf++) {
            const int row = mt * 16 + qr + hf * 8;
            float f0 = leaky(acc[nf][hf * 2 + 0] + b0);
            float f1 = leaky(acc[nf][hf * 2 + 1] + b1);
            uint32_t hi, lo; split2(f0, f1, hi, lo);
            *(uint32_t*)(smem + outHi + (size_t)row * strideOut + (size_t)col * 2) = hi;
            *(uint32_t*)(smem + outLo + (size_t)row * strideOut + (size_t)col * 2) = lo;
        }
    }
}

// ---------------- final epilogue: bias -> gmem fp32 (+ optional chain into A) ----------
template <int CHAIN>
__device__ __forceinline__ void epi_final(const float acc[][4], const float* bias,
                                          float* __restrict__ gout, uint8_t* smem,
                                          int mt, int n0, int lane)
{
    const int qr = lane >> 2, qc = (lane & 3) * 2;
    float vv[8][4];
#pragma unroll
    for (int nf = 0; nf < 8; nf++) {
        const int col = n0 + nf * 8 + qc;
        const float b0 = bias[col], b1 = bias[col + 1];
#pragma unroll
        for (int hf = 0; hf < 2; hf++) {
            vv[nf][hf * 2 + 0] = acc[nf][hf * 2 + 0] + b0;
            vv[nf][hf * 2 + 1] = acc[nf][hf * 2 + 1] + b1;
            const int row = mt * 16 + qr + hf * 8;
            *(float2*)&gout[(size_t)row * DIM + col] =
                make_float2(vv[nf][hf * 2 + 0], vv[nf][hf * 2 + 1]);
        }
    }
    if (CHAIN) {
        __syncthreads();   // all warps done reading A before we overwrite it
#pragma unroll
        for (int nf = 0; nf < 8; nf++) {
            const int col = n0 + nf * 8 + qc;
#pragma unroll
            for (int hf = 0; hf < 2; hf++) {
                const int row = mt * 16 + qr + hf * 8;
                uint32_t hi, lo; split2(vv[nf][hf * 2 + 0], vv[nf][hf * 2 + 1], hi, lo);
                *(uint32_t*)(smem + OFF_AH + (size_t)row * STR_A + (size_t)col * 2) = hi;
                *(uint32_t*)(smem + OFF_AL + (size_t)row * STR_A + (size_t)col * 2) = lo;
            }
        }
    }
}

__device__ __forceinline__ void stage_w(uint8_t* smem, const uint8_t* g, int bytes, int tid) {
    const uint4* s4 = (const uint4*)g;
    uint4* d4 = (uint4*)(smem + OFF_W);
    for (int i = tid; i < bytes / 16; i += NT) d4[i] = s4[i];
}

// ---------------- one full 3-layer MLP (A[64][128] in smem -> gout) ----------------
template <int CHAIN>
__device__ __forceinline__ void run_mlp(uint8_t* smem, uint32_t SB, const uint8_t* wb,
                                        const float* bias, float* __restrict__ gout, int tid)
{
    const int lane = tid & 31, w = tid >> 5;
    const int mt = w & 3;
    float acc[8][4];

    // L1: [64,128] @ W1[128->64]
    stage_w(smem, wb + WL1H, 34816, tid);
    __syncthreads();
    mma_layer<8, 4>(SB + OFF_AH, SB + OFF_AL, STR_A,
                    SB + OFF_W, SB + OFF_W + 17408, STR_A, mt, (w >> 2) * 32, lane, acc);
    epi_mid<4>(acc, bias, smem, OFF_BH, OFF_BL, STR_B, mt, (w >> 2) * 32, lane);
    __syncthreads();

    // L2: [64,64] @ W2[64->64]
    stage_w(smem, wb + WL2H, 18432, tid);
    __syncthreads();
    mma_layer<4, 4>(SB + OFF_BH, SB + OFF_BL, STR_B,
                    SB + OFF_W, SB + OFF_W + 9216, STR_B, mt, (w >> 2) * 32, lane, acc);
    epi_mid<4>(acc, bias + 64, smem, OFF_AH, OFF_AL, STR_A, mt, (w >> 2) * 32, lane);
    __syncthreads();

    // L3: [64,64] @ W3[64->128]
    stage_w(smem, wb + WL3H, 36864, tid);
    __syncthreads();
    mma_layer<4, 8>(SB + OFF_AH, SB + OFF_AL, STR_A,
                    SB + OFF_W, SB + OFF_W + 18432, STR_B, mt, (w >> 2) * 64, lane, acc);
    epi_final<CHAIN>(acc, bias + 128, gout, smem, mt, (w >> 2) * 64, lane);
}

// ---------------- fused per-level kernel ----------------
// mode 0: inv-MLP on hin rows (level-0 sources). mode 1: gather -> and-MLP -> (inv-MLP)
__global__ __launch_bounds__(NT, 2)
void fused_kernel(const float* __restrict__ hin, float* __restrict__ h,
                  const int* __restrict__ src, const int* __restrict__ mask,
                  const float* ab1, const float* ab2, const float* ab3,
                  const float* ib1, const float* ib2, const float* ib3,
                  int lvl, int mode, int do_inv)
{
    extern __shared__ __align__(16) uint8_t smem[];
    const uint32_t SB = smem_u32(smem);
    const int tid = threadIdx.x;
    const int lane = tid & 31, w = tid >> 5;
    float* ginv = g_inv;
    float* BIAS = (float*)(smem + OFF_BIAS);

    if (tid < 64) {
        BIAS[tid] = ab1[tid];       BIAS[64 + tid] = ab2[tid];
        BIAS[256 + tid] = ib1[tid]; BIAS[320 + tid] = ib2[tid];
    }
    if (tid < 128) { BIAS[128 + tid] = ab3[tid]; BIAS[384 + tid] = ib3[tid]; }

    const int nodebase = blockIdx.x * 64;

    // ---- build A tile (hi/lo bf16) ----
    if (mode == 0) {
        const float4* in4 = (const float4*)(hin + (size_t)nodebase * DIM);
        for (int i = tid; i < 64 * 32; i += NT) {
            const int row = i >> 5, c4 = i & 31;
            float4 x = in4[(size_t)row * 32 + c4];
            uint32_t h0, l0, h1, l1;
            split2(x.x, x.y, h0, l0);
            split2(x.z, x.w, h1, l1);
            const size_t off = (size_t)row * STR_A + (size_t)c4 * 8;
            *(uint32_t*)(smem + OFF_AH + off) = h0;
            *(uint32_t*)(smem + OFF_AH + off + 4) = h1;
            *(uint32_t*)(smem + OFF_AL + off) = l0;
            *(uint32_t*)(smem + OFF_AL + off + 4) = l1;
        }
    } else {
        for (int rr = 0; rr < 8; rr++) {
            const int row = w * 8 + rr;
            const int node = nodebase + row;
            int s = 0, m = 0;
            if (lane < 16) { s = src[node * DEG + lane]; m = mask[node * DEG + lane]; }
            float4 acc = make_float4(0.f, 0.f, 0.f, 0.f);
#pragma unroll
            for (int e = 0; e < DEG; e++) {
                int se = __shfl_sync(0xffffffffu, s, e);
                int me = __shfl_sync(0xffffffffu, m, e);
                const float4* rp = (const float4*)((me ? ginv : h) + (size_t)se * DIM);
                float4 v = rp[lane];
                acc.x += v.x; acc.y += v.y; acc.z += v.z; acc.w += v.w;
            }
            const float s16 = 0.0625f;
            acc.x *= s16; acc.y *= s16; acc.z *= s16; acc.w *= s16;
            uint32_t h0, l0, h1, l1;
            split2(acc.x, acc.y, h0, l0);
            split2(acc.z, acc.w, h1, l1);
            const size_t off = (size_t)row * STR_A + (size_t)lane * 8;
            *(uint32_t*)(smem + OFF_AH + off) = h0;
            *(uint32_t*)(smem + OFF_AH + off + 4) = h1;
            *(uint32_t*)(smem + OFF_AL + off) = l0;
            *(uint32_t*)(smem + OFF_AL + off + 4) = l1;
        }
    }
    __syncthreads();

    if (mode == 0) {
        float* gout = ginv + (size_t)nodebase * DIM;
        run_mlp<0>(smem, SB, g_wb + WBLOB, BIAS + 256, gout, tid);
    } else {
        float* gout = h + ((size_t)(lvl + 1) * NPL + (size_t)nodebase) * DIM;
        if (do_inv) {
            run_mlp<1>(smem, SB, g_wb, BIAS, gout, tid);
            float* gi = ginv + ((size_t)(lvl + 1) * NPL + (size_t)nodebase) * DIM;
            run_mlp<0>(smem, SB, g_wb + WBLOB, BIAS + 256, gi, tid);
        } else {
            run_mlp<0>(smem, SB, g_wb, BIAS, gout, tid);
        }
    }
}

// ---------------------------------------------------------------------------
extern "C" void kernel_launch(void* const* d_in, const int* in_sizes, int n_in,
                              void* d_out, int out_size)
{
    (void)in_sizes; (void)n_in; (void)out_size;
    const float* h_in  = (const float*)d_in[0];
    const int*   esrc  = (const int*)d_in[1];
    const int*   emask = (const int*)d_in[2];
    const float* iw1 = (const float*)d_in[3];
    const float* ib1 = (const float*)d_in[4];
    const float* iw2 = (const float*)d_in[5];
    const float* ib2 = (const float*)d_in[6];
    const float* iw3 = (const float*)d_in[7];
    const float* ib3 = (const float*)d_in[8];
    const float* aw1 = (const float*)d_in[9];
    const float* ab1 = (const float*)d_in[10];
    const float* aw2 = (const float*)d_in[11];
    const float* ab2 = (const float*)d_in[12];
    const float* aw3 = (const float*)d_in[13];
    const float* ab3 = (const float*)d_in[14];

    float* h = (float*)d_out;

    static bool once = false;
    if (!once) {
        cudaFuncSetAttribute(fused_kernel, cudaFuncAttributeMaxDynamicSharedMemorySize, SM_TOTAL);
        once = true;
    }

    // level-0 rows of the output are the input rows
    cudaMemcpyAsync(h, h_in, (size_t)NPL * DIM * sizeof(float), cudaMemcpyDeviceToDevice, 0);

    prep_weights<<<6, 256>>>(aw1, aw2, aw3, iw1, iw2, iw3);

    const int grid = NPL / 64;   // 256 CTAs

    // inv features of level-0 sources
    fused_kernel<<<grid, NT, SM_TOTAL>>>(h_in, h, esrc, emask,
                                         ab1, ab2, ab3, ib1, ib2, ib3, 0, 0, 0);

    for (int lvl = 0; lvl < L_LEV - 1; lvl++) {
        const int* s = esrc  + (size_t)lvl * NPL * DEG;
        const int* m = emask + (size_t)lvl * NPL * DEG;
        fused_kernel<<<grid, NT, SM_TOTAL>>>(h_in, h, s, m,
                                             ab1, ab2, ab3, ib1, ib2, ib3,
                                             lvl, 1, (lvl < L_LEV - 2) ? 1 : 0);
    }
}